// round 3
// baseline (speedup 1.0000x reference)
#include <cuda_runtime.h>
#include <math.h>

// Problem constants
#define NNODE 2048
#define NEDGE 4096
#define LF    49          // full L
#define LR    16          // reduced
#define MMID  25
#define NYR   3
#define CCH   128
#define HID   128
#define XLC   (LF*CCH)    // 6272
#define T_W   1225        // 49*25 / 25*49 flattened
#define FEATW 2064        // 16*129
#define MSGW  2048        // 16*128

__device__ float g_xe  [NEDGE*HID];
__device__ float g_xm  [NEDGE*LF];
__device__ float g_ym  [NEDGE*LF];
__device__ float g_t   [NEDGE*T_W];
__device__ float g_mid [NEDGE*MMID];
__device__ float g_A   [NEDGE*LF];
__device__ float g_feat[NEDGE*FEATW];
__device__ float g_h   [NEDGE*HID];
__device__ float g_h2  [NEDGE*MSGW];
__device__ float g_sh  [NEDGE*LR*CCH];
__device__ float g_msg [NEDGE*NYR*MSGW];
__device__ float g_m1  [NEDGE*NYR*HID];
__device__ float g_m2  [NEDGE*NYR*MSGW];

__device__ __forceinline__ float silu_f(float v) {
    return v / (1.0f + __expf(-v));
}

// ---------------------------------------------------------------------------
// Generic tiled SGEMM: C[M,N] = A[M,K] * B[K,N], row-major.
// EPI: 0 = plain, 1 = bias+silu, 2 = bias+silu then *= xe[(row/3)*128+col]
// ---------------------------------------------------------------------------
template<int EPI>
__global__ __launch_bounds__(256)
void sgemm_k(const float* __restrict__ A, const float* __restrict__ B,
             const float* __restrict__ bias, const float* __restrict__ xe,
             float* __restrict__ C, int M, int N, int K)
{
    __shared__ float As[16][68];   // padded for float4 + conflict avoidance
    __shared__ float Bs[16][64];

    int tid = threadIdx.x;
    int bm0 = blockIdx.y * 64;
    int bn0 = blockIdx.x * 64;
    int ty = tid >> 4, tx = tid & 15;

    float acc[4][4];
#pragma unroll
    for (int i = 0; i < 4; i++)
#pragma unroll
        for (int j = 0; j < 4; j++) acc[i][j] = 0.0f;

    int nk = (K + 15) >> 4;
    for (int t = 0; t < nk; t++) {
        int k0 = t << 4;
#pragma unroll
        for (int i = 0; i < 4; i++) {
            int idx = tid + i * 256;
            int r = idx >> 4, kk = idx & 15;
            int gr = bm0 + r, gk = k0 + kk;
            As[kk][r] = (gr < M && gk < K) ? A[gr * K + gk] : 0.0f;
        }
#pragma unroll
        for (int i = 0; i < 4; i++) {
            int idx = tid + i * 256;
            int kr = idx >> 6, c = idx & 63;
            int gk = k0 + kr, gc = bn0 + c;
            Bs[kr][c] = (gk < K && gc < N) ? B[gk * N + gc] : 0.0f;
        }
        __syncthreads();
#pragma unroll
        for (int kk = 0; kk < 16; kk++) {
            float4 av = *(const float4*)&As[kk][ty * 4];
            float4 bv = *(const float4*)&Bs[kk][tx * 4];
            float a0 = av.x, a1 = av.y, a2 = av.z, a3 = av.w;
            float b0 = bv.x, b1 = bv.y, b2 = bv.z, b3 = bv.w;
            acc[0][0] = fmaf(a0, b0, acc[0][0]); acc[0][1] = fmaf(a0, b1, acc[0][1]);
            acc[0][2] = fmaf(a0, b2, acc[0][2]); acc[0][3] = fmaf(a0, b3, acc[0][3]);
            acc[1][0] = fmaf(a1, b0, acc[1][0]); acc[1][1] = fmaf(a1, b1, acc[1][1]);
            acc[1][2] = fmaf(a1, b2, acc[1][2]); acc[1][3] = fmaf(a1, b3, acc[1][3]);
            acc[2][0] = fmaf(a2, b0, acc[2][0]); acc[2][1] = fmaf(a2, b1, acc[2][1]);
            acc[2][2] = fmaf(a2, b2, acc[2][2]); acc[2][3] = fmaf(a2, b3, acc[2][3]);
            acc[3][0] = fmaf(a3, b0, acc[3][0]); acc[3][1] = fmaf(a3, b1, acc[3][1]);
            acc[3][2] = fmaf(a3, b2, acc[3][2]); acc[3][3] = fmaf(a3, b3, acc[3][3]);
        }
        __syncthreads();
    }

#pragma unroll
    for (int i = 0; i < 4; i++) {
        int row = bm0 + ty * 4 + i;
        if (row >= M) continue;
#pragma unroll
        for (int j = 0; j < 4; j++) {
            int col = bn0 + tx * 4 + j;
            if (col >= N) continue;
            float v = acc[i][j];
            if (EPI >= 1) { v += bias[col]; v = silu_f(v); }
            if (EPI == 2) { v *= xe[(row / 3) * 128 + col]; }
            C[row * N + col] = v;
        }
    }
}

// ---------------------------------------------------------------------------
// xm[e,l] = mean_c x[src,l,c]; ym[e,l] = mean_c x[dst,l,c]
// ---------------------------------------------------------------------------
__global__ void k_xmym(const float* __restrict__ x, const int* __restrict__ eidx,
                       float* __restrict__ xm, float* __restrict__ ym)
{
    int e = blockIdx.x, tid = threadIdx.x;
    int lane = tid & 31, warp = tid >> 5;
    int src = eidx[e], dst = eidx[NEDGE + e];
    const float* ps = x + src * XLC;
    const float* pt = x + dst * XLC;
    for (int l = warp; l < LF; l += 4) {
        const float* a = ps + l * 128;
        const float* b = pt + l * 128;
        float s = a[lane] + a[lane + 32] + a[lane + 64] + a[lane + 96];
        float u = b[lane] + b[lane + 32] + b[lane + 64] + b[lane + 96];
#pragma unroll
        for (int o = 16; o > 0; o >>= 1) {
            s += __shfl_xor_sync(0xffffffffu, s, o);
            u += __shfl_xor_sync(0xffffffffu, u, o);
        }
        if (lane == 0) {
            xm[e * LF + l] = s * (1.0f / 128.0f);
            ym[e * LF + l] = u * (1.0f / 128.0f);
        }
    }
}

// mid[e,o] = sum_j ym[e,j] * t[e, j*25 + o]   (o<25, j<49)
__global__ void k_mid(const float* __restrict__ ym, const float* __restrict__ t,
                      float* __restrict__ mid)
{
    int e = blockIdx.x, tid = threadIdx.x;
    __shared__ float ys[LF];
    if (tid < LF) ys[tid] = ym[e * LF + tid];
    __syncthreads();
    if (tid < MMID) {
        const float* tp = t + e * T_W + tid;
        float s = 0.0f;
#pragma unroll
        for (int j = 0; j < LF; j++) s = fmaf(ys[j], tp[j * MMID], s);
        mid[e * MMID + tid] = s;
    }
}

// A[e,o] (+)= sum_j mid[e,j] * t[e, j*49 + o]   (o<49, j<25)
template<int ACC>
__global__ void k_contract(const float* __restrict__ mid, const float* __restrict__ t,
                           float* __restrict__ Aout)
{
    int e = blockIdx.x, tid = threadIdx.x;
    __shared__ float ms[MMID];
    if (tid < MMID) ms[tid] = mid[e * MMID + tid];
    __syncthreads();
    if (tid < LF) {
        const float* tp = t + e * T_W + tid;
        float s = ACC ? Aout[e * LF + tid] : 0.0f;
#pragma unroll
        for (int j = 0; j < MMID; j++) s = fmaf(ms[j], tp[j * LF], s);
        Aout[e * LF + tid] = s;
    }
}

// ---------------------------------------------------------------------------
// node_interaction front: ne = wig_node^T @ x[node][:16], feat = [ne | mean*g]
// feat[e, i*129 + c] = ne[i,c];  feat[e, i*129+128] = mean_c(ne[i]) * g[other,i]
// ---------------------------------------------------------------------------
__global__ void k_feat(const float* __restrict__ x, const float* __restrict__ glovec,
                       const float* __restrict__ wign, const int* __restrict__ eidx,
                       int node_off, int other_off, float* __restrict__ feat)
{
    int e = blockIdx.x, tid = threadIdx.x;   // 128 threads = channel c
    __shared__ float wigS[256];
    __shared__ float gS[16];
    __shared__ float red[4];
    int node  = eidx[node_off  + e];
    int other = eidx[other_off + e];
    wigS[tid]       = wign[e * 256 + tid];
    wigS[tid + 128] = wign[e * 256 + 128 + tid];
    if (tid < 16) gS[tid] = glovec[other * LR + tid];
    __syncthreads();

    float xr[16];
    const float* xp = x + node * XLC;
#pragma unroll
    for (int j = 0; j < 16; j++) xr[j] = xp[j * 128 + tid];

    float* fp = feat + e * FEATW;
    for (int i = 0; i < 16; i++) {
        float a = 0.0f;
#pragma unroll
        for (int j = 0; j < 16; j++) a = fmaf(wigS[j * 16 + i], xr[j], a);
        fp[i * 129 + tid] = a;
        float s = a;
#pragma unroll
        for (int o = 16; o > 0; o >>= 1) s += __shfl_xor_sync(0xffffffffu, s, o);
        if ((tid & 31) == 0) red[tid >> 5] = s;
        __syncthreads();
        if (tid == 0)
            fp[i * 129 + 128] = (red[0] + red[1] + red[2] + red[3]) * (1.0f / 128.0f) * gS[i];
        __syncthreads();
    }
}

// sh[e,i,c] (+)= sum_j wig_node[e,i,j] * h2[e, j*128 + c]
template<int ACC>
__global__ void k_sh(const float* __restrict__ wign, const float* __restrict__ h2,
                     float* __restrict__ sh)
{
    int e = blockIdx.x, tid = threadIdx.x;   // 128 threads
    __shared__ float wigS[256];
    wigS[tid]       = wign[e * 256 + tid];
    wigS[tid + 128] = wign[e * 256 + 128 + tid];
    __syncthreads();
    float hr[16];
    const float* hp = h2 + e * MSGW;
#pragma unroll
    for (int j = 0; j < 16; j++) hr[j] = hp[j * 128 + tid];
    float* sp = sh + e * MSGW;
#pragma unroll
    for (int i = 0; i < 16; i++) {
        float s = 0.0f;
#pragma unroll
        for (int j = 0; j < 16; j++) s = fmaf(wigS[i * 16 + j], hr[j], s);
        if (ACC) sp[i * 128 + tid] += s; else sp[i * 128 + tid] = s;
    }
}

// ---------------------------------------------------------------------------
// z[l,c] = 2*(xs+xt) + A[l] + (l<16 ? sh[l,c] : 0)
// msg[e, n*16+r, c] = sum_l wigner[e,(n,r),l] * z[l,c]
// ---------------------------------------------------------------------------
__global__ __launch_bounds__(256)
void k_rotmsg(const float* __restrict__ x, const int* __restrict__ eidx,
              const float* __restrict__ Aarr, const float* __restrict__ sh,
              const float* __restrict__ wigner, float* __restrict__ msg)
{
    int e = blockIdx.x, tid = threadIdx.x;
    __shared__ float zs[LF * 128];      // 25 KB
    __shared__ float wgS[48 * 49];      // 9.2 KB
    int src = eidx[e], dst = eidx[NEDGE + e];
    const float* xs = x + src * XLC;
    const float* xt = x + dst * XLC;
    const float* shp = sh + e * MSGW;
    const float* Ap  = Aarr + e * LF;
    for (int idx = tid; idx < LF * 128; idx += 256) {
        int l = idx >> 7, c = idx & 127;
        float v = 2.0f * (xs[idx] + xt[idx]) + Ap[l];
        if (l < 16) v += shp[l * 128 + c];
        zs[idx] = v;
    }
    const float* wp = wigner + e * (48 * 49);
    for (int idx = tid; idx < 48 * 49; idx += 256) wgS[idx] = wp[idx];
    __syncthreads();

    int cg = tid & 63, grp = tid >> 6;      // grp handles 12 rows, cg -> 2 channels
    float2 acc[12];
#pragma unroll
    for (int rr = 0; rr < 12; rr++) { acc[rr].x = 0.0f; acc[rr].y = 0.0f; }
    const float2* z2 = (const float2*)zs;
    for (int l = 0; l < LF; l++) {
        float2 zv = z2[l * 64 + cg];
#pragma unroll
        for (int rr = 0; rr < 12; rr++) {
            float w = wgS[(grp * 12 + rr) * LF + l];
            acc[rr].x = fmaf(w, zv.x, acc[rr].x);
            acc[rr].y = fmaf(w, zv.y, acc[rr].y);
        }
    }
    float* mp = msg + e * (NYR * MSGW);
#pragma unroll
    for (int rr = 0; rr < 12; rr++) {
        int row = grp * 12 + rr;
        ((float2*)(mp + row * 128))[cg] = acc[rr];
    }
}

// ---------------------------------------------------------------------------
// mm[r,c] = mean_n m2[e*3+n, r*128+c]; out[e,b,c] = invsqrt3 * sum_r winv[b,r]*mm[r,c]
// ---------------------------------------------------------------------------
__global__ __launch_bounds__(256)
void k_out(const float* __restrict__ m2, const float* __restrict__ winv,
           float* __restrict__ out)
{
    int e = blockIdx.x, tid = threadIdx.x;
    __shared__ float mmS[16 * 128];
    __shared__ float wvS[LF * 16];
    const float* mp = m2 + e * (NYR * MSGW);
    for (int idx = tid; idx < 2048; idx += 256)
        mmS[idx] = (mp[idx] + mp[idx + 2048] + mp[idx + 4096]) * (1.0f / 3.0f);
    const float* wp = winv + e * (LF * 16);
    for (int idx = tid; idx < LF * 16; idx += 256) wvS[idx] = wp[idx];
    __syncthreads();

    const float INV3 = 0.5773502691896258f;
    int cg = tid & 63, grp = tid >> 6;
    const float2* mm2 = (const float2*)mmS;
    float* op = out + e * XLC;
    for (int b = grp; b < LF; b += 4) {
        float2 s; s.x = 0.0f; s.y = 0.0f;
#pragma unroll
        for (int r = 0; r < 16; r++) {
            float w = wvS[b * 16 + r];
            float2 mv = mm2[r * 64 + cg];
            s.x = fmaf(w, mv.x, s.x);
            s.y = fmaf(w, mv.y, s.y);
        }
        s.x *= INV3; s.y *= INV3;
        ((float2*)(op + b * 128))[cg] = s;
    }
}

// ---------------------------------------------------------------------------
extern "C" void kernel_launch(void* const* d_in, const int* in_sizes, int n_in,
                              void* d_out, int out_size)
{
    const float* x      = (const float*)d_in[0];
    const float* glovec = (const float*)d_in[2];
    const float* x_edge = (const float*)d_in[3];
    const int*   eidx   = (const int*)  d_in[4];
    const float* W_cg1  = (const float*)d_in[8];
    const float* W_cg21 = (const float*)d_in[9];
    const float* W_cg22 = (const float*)d_in[10];
    const float* Wn1a   = (const float*)d_in[11];
    const float* bn1a   = (const float*)d_in[12];
    const float* Wn1b   = (const float*)d_in[13];
    const float* bn1b   = (const float*)d_in[14];
    const float* Wn2a   = (const float*)d_in[15];
    const float* bn2a   = (const float*)d_in[16];
    const float* Wn2b   = (const float*)d_in[17];
    const float* bn2b   = (const float*)d_in[18];
    const float* Wd     = (const float*)d_in[19];
    const float* bd     = (const float*)d_in[20];
    const float* Wp1    = (const float*)d_in[21];
    const float* bp1    = (const float*)d_in[22];
    const float* Wp2    = (const float*)d_in[23];
    const float* bp2    = (const float*)d_in[24];
    const float* wigner = (const float*)d_in[25];
    const float* winv   = (const float*)d_in[26];
    const float* wign   = (const float*)d_in[27];
    float* out = (float*)d_out;

    float *p_xe, *p_xm, *p_ym, *p_t, *p_mid, *p_A, *p_feat, *p_h, *p_h2,
          *p_sh, *p_msg, *p_m1, *p_m2;
    cudaGetSymbolAddress((void**)&p_xe,   g_xe);
    cudaGetSymbolAddress((void**)&p_xm,   g_xm);
    cudaGetSymbolAddress((void**)&p_ym,   g_ym);
    cudaGetSymbolAddress((void**)&p_t,    g_t);
    cudaGetSymbolAddress((void**)&p_mid,  g_mid);
    cudaGetSymbolAddress((void**)&p_A,    g_A);
    cudaGetSymbolAddress((void**)&p_feat, g_feat);
    cudaGetSymbolAddress((void**)&p_h,    g_h);
    cudaGetSymbolAddress((void**)&p_h2,   g_h2);
    cudaGetSymbolAddress((void**)&p_sh,   g_sh);
    cudaGetSymbolAddress((void**)&p_msg,  g_msg);
    cudaGetSymbolAddress((void**)&p_m1,   g_m1);
    cudaGetSymbolAddress((void**)&p_m2,   g_m2);

    auto grid = [](int M, int N) { return dim3((N + 63) / 64, (M + 63) / 64); };

    // 1. xe = silu(x_edge @ Wd + bd)
    sgemm_k<1><<<grid(NEDGE, HID), 256>>>(x_edge, Wd, bd, nullptr, p_xe, NEDGE, HID, 128);

    // 2. channel means of gathered features
    k_xmym<<<NEDGE, 128>>>(x, eidx, p_xm, p_ym);

    // 3. CG bilinears -> A[e,l]
    sgemm_k<0><<<grid(NEDGE, T_W), 256>>>(p_xm, W_cg1, nullptr, nullptr, p_t, NEDGE, T_W, LF);
    k_mid<<<NEDGE, 64>>>(p_ym, p_t, p_mid);
    sgemm_k<0><<<grid(NEDGE, T_W), 256>>>(p_xm, W_cg21, nullptr, nullptr, p_t, NEDGE, T_W, LF);
    k_contract<0><<<NEDGE, 64>>>(p_mid, p_t, p_A);
    sgemm_k<0><<<grid(NEDGE, T_W), 256>>>(p_ym, W_cg22, nullptr, nullptr, p_t, NEDGE, T_W, LF);
    k_contract<1><<<NEDGE, 64>>>(p_mid, p_t, p_A);

    // 4. node_interaction 1 (src features, dst glovec)
    k_feat<<<NEDGE, 128>>>(x, glovec, wign, eidx, 0, NEDGE, p_feat);
    sgemm_k<1><<<grid(NEDGE, HID), 256>>>(p_feat, Wn1a, bn1a, nullptr, p_h, NEDGE, HID, FEATW);
    sgemm_k<1><<<grid(NEDGE, MSGW), 256>>>(p_h, Wn1b, bn1b, nullptr, p_h2, NEDGE, MSGW, HID);
    k_sh<0><<<NEDGE, 128>>>(wign, p_h2, p_sh);

    // 5. node_interaction 2 (dst features, src glovec)
    k_feat<<<NEDGE, 128>>>(x, glovec, wign, eidx, NEDGE, 0, p_feat);
    sgemm_k<1><<<grid(NEDGE, HID), 256>>>(p_feat, Wn2a, bn2a, nullptr, p_h, NEDGE, HID, FEATW);
    sgemm_k<1><<<grid(NEDGE, MSGW), 256>>>(p_h, Wn2b, bn2b, nullptr, p_h2, NEDGE, MSGW, HID);
    k_sh<1><<<NEDGE, 128>>>(wign, p_h2, p_sh);

    // 6. fused z-build + rotate -> msg [E*NY, 2048]
    k_rotmsg<<<NEDGE, 256>>>(x, eidx, p_A, p_sh, wigner, p_msg);

    // 7. edge MLP with xe modulation
    sgemm_k<2><<<grid(NEDGE * NYR, HID), 256>>>(p_msg, Wp1, bp1, p_xe, p_m1,
                                                NEDGE * NYR, HID, MSGW);
    sgemm_k<1><<<grid(NEDGE * NYR, MSGW), 256>>>(p_m1, Wp2, bp2, nullptr, p_m2,
                                                 NEDGE * NYR, MSGW, HID);

    // 8. NY-mean + inverse rotation -> output [E,49,128]
    k_out<<<NEDGE, 256>>>(p_m2, winv, out);
}

// round 5
// speedup vs baseline: 2.4838x; 2.4838x over previous
#include <cuda_runtime.h>
#include <cstdint>
#include <math.h>

// ---------------- problem constants ----------------
#define NNODE 2048
#define NEDGE 4096
#define LF    49
#define LR    16
#define MMID  25
#define NYR   3
#define CCH   128
#define HID   128
#define XLC   (LF*CCH)      // 6272
#define FEATW 2064          // 16*129
#define MSGW  2048          // 16*128
#define TPAD  1280          // padded 1225
#define KCG   64            // padded 49

// ---------------- device scratch ----------------
__device__ __align__(16) float g_WdT  [128*128];
__device__ __align__(16) float g_Wn1aT[128*FEATW];
__device__ __align__(16) float g_Wn1bT[2048*128];
__device__ __align__(16) float g_Wn2aT[128*FEATW];
__device__ __align__(16) float g_Wn2bT[2048*128];
__device__ __align__(16) float g_Wp1T [128*2048];
__device__ __align__(16) float g_Wp2T [2048*128];
__device__ __align__(16) float g_Wc1T [TPAD*KCG];
__device__ __align__(16) float g_Wc2T [TPAD*KCG];
__device__ __align__(16) float g_Wc3T [TPAD*KCG];
__device__ __align__(16) float g_xe   [NEDGE*HID];
__device__ __align__(16) float g_xm   [NEDGE*KCG];
__device__ __align__(16) float g_ym   [NEDGE*KCG];
__device__ __align__(16) float g_t    [NEDGE*TPAD];
__device__ __align__(16) float g_mid  [NEDGE*MMID];
__device__ __align__(16) float g_A    [NEDGE*LF];
__device__ __align__(16) float g_feat [NEDGE*FEATW];
__device__ __align__(16) float g_h    [NEDGE*HID];
__device__ __align__(16) float g_h2   [NEDGE*MSGW];
__device__ __align__(16) float g_sh   [NEDGE*LR*CCH];
__device__ __align__(16) float g_msg  [NEDGE*NYR*MSGW];
__device__ __align__(16) float g_m1   [NEDGE*NYR*HID];
__device__ __align__(16) float g_m2   [NEDGE*NYR*MSGW];
__device__ __align__(16) float g_part [4*12288*128];

__device__ __forceinline__ float silu_f(float v) { return v / (1.0f + __expf(-v)); }

__device__ __forceinline__ uint32_t f2tf32(float f) {
    uint32_t r;
    asm("cvt.rna.tf32.f32 %0, %1;" : "=r"(r) : "f"(f));
    return r;
}

__device__ __forceinline__ void mma8(float* d, const uint32_t* a, const uint32_t* b) {
    asm volatile(
        "mma.sync.aligned.m16n8k8.row.col.f32.tf32.tf32.f32 "
        "{%0,%1,%2,%3}, {%4,%5,%6,%7}, {%8,%9}, {%0,%1,%2,%3};"
        : "+f"(d[0]), "+f"(d[1]), "+f"(d[2]), "+f"(d[3])
        : "r"(a[0]), "r"(a[1]), "r"(a[2]), "r"(a[3]), "r"(b[0]), "r"(b[1]));
}

// ---------------------------------------------------------------------------
// tf32 mma.sync GEMM: C[M,N] = A[M,K] @ BT[N,K]^T   (row-major A, BT)
// CTA tile 128x128, K chunks of 32, 8 warps (2x4), warp tile 64x32.
// grid = (Ntiles, Mtiles, nsplit); split z handles chunks [z*cpz ..) writing
// C + z*M*ldc (raw, EPI must be 0 when nsplit>1).
// EPI: 0=raw, 1=bias+silu, 2=bias+silu then *= xe[(row/3)*128+col]
// Requires M%128==0, K%4==0.
// ---------------------------------------------------------------------------
#define LDA 36
#define ATILE (128*LDA)          // uint32 elements per A (or B) tile
#define BUFSZ (2*ATILE)          // A+B per buffer
#define DYN_SMEM (2*BUFSZ*4)     // 73728 bytes

template<int EPI>
__global__ __launch_bounds__(256, 1)
void tgemm(const float* __restrict__ A, const float* __restrict__ BT,
           const float* __restrict__ bias, const float* __restrict__ xe,
           float* __restrict__ C, int M, int Nreal, int K, int ldc,
           int chunksTotal, int chunksPerZ)
{
    extern __shared__ uint32_t sm[];
    const int tid  = threadIdx.x;
    const int lane = tid & 31;
    const int warp = tid >> 5;
    const int wm = warp >> 2, wn = warp & 3;
    const int g = lane >> 2, t = lane & 3;

    const int bm0 = blockIdx.y * 128;
    const int bn0 = blockIdx.x * 128;
    const int z   = blockIdx.z;
    const int c0  = z * chunksPerZ;
    int cend = c0 + chunksPerZ; if (cend > chunksTotal) cend = chunksTotal;

    float acc[4][4][4];
#pragma unroll
    for (int i = 0; i < 4; i++)
#pragma unroll
        for (int j = 0; j < 4; j++)
#pragma unroll
            for (int q = 0; q < 4; q++) acc[i][j][q] = 0.0f;

    // per-thread load slots: 4 float4 for A, 4 for B
    const int lr  = tid >> 1;              // 0..127 row
    const int lsg = (tid & 1) * 4;         // col segment base (x2 iterations of 16)
    float4 pa[4], pb[4];

    auto loadRegs = [&](int c) {
        const int kbase = c * 32;
#pragma unroll
        for (int i = 0; i < 2; i++) {
            int gk = kbase + (lsg + i * 2) * 4 - lsg * 4;   // dummy to keep structure
            (void)gk;
        }
        // A: rows lr, lr+? : each thread loads 2 float4 from row lr (cols lsg*4, lsg*4+32? )
        // simpler mapping: idx = tid + i*256 -> r = idx>>3, seg = idx&7
#pragma unroll
        for (int i = 0; i < 4; i++) {
            int idx = tid + i * 256;
            int r = idx >> 3, seg = idx & 7;
            int gk = kbase + seg * 4;
            float4 v = make_float4(0.f, 0.f, 0.f, 0.f);
            if (gk < K) v = *(const float4*)(A + (size_t)(bm0 + r) * K + gk);
            pa[i] = v;
        }
#pragma unroll
        for (int i = 0; i < 4; i++) {
            int idx = tid + i * 256;
            int r = idx >> 3, seg = idx & 7;
            int gn = bn0 + r, gk = kbase + seg * 4;
            float4 v = make_float4(0.f, 0.f, 0.f, 0.f);
            if (gn < Nreal && gk < K) v = *(const float4*)(BT + (size_t)gn * K + gk);
            pb[i] = v;
        }
    };

    auto storeRegs = [&](int b) {
        uint32_t* As = sm + b * BUFSZ;
        uint32_t* Bs = As + ATILE;
#pragma unroll
        for (int i = 0; i < 4; i++) {
            int idx = tid + i * 256;
            int r = idx >> 3, seg = idx & 7;
            uint32_t* p = As + r * LDA + seg * 4;
            p[0] = f2tf32(pa[i].x); p[1] = f2tf32(pa[i].y);
            p[2] = f2tf32(pa[i].z); p[3] = f2tf32(pa[i].w);
        }
#pragma unroll
        for (int i = 0; i < 4; i++) {
            int idx = tid + i * 256;
            int r = idx >> 3, seg = idx & 7;
            uint32_t* p = Bs + r * LDA + seg * 4;
            p[0] = f2tf32(pb[i].x); p[1] = f2tf32(pb[i].y);
            p[2] = f2tf32(pb[i].z); p[3] = f2tf32(pb[i].w);
        }
    };

    loadRegs(c0);
    for (int c = c0; c < cend; ++c) {
        int b = (c - c0) & 1;
        storeRegs(b);
        __syncthreads();
        if (c + 1 < cend) loadRegs(c + 1);

        const uint32_t* As = sm + b * BUFSZ;
        const uint32_t* Bs = As + ATILE;
#pragma unroll
        for (int kk = 0; kk < 4; kk++) {
            const int k0 = kk * 8;
            uint32_t af[4][4], bf[4][2];
#pragma unroll
            for (int i = 0; i < 4; i++) {
                int mb = wm * 64 + i * 16;
                af[i][0] = As[(mb + g)     * LDA + k0 + t];
                af[i][1] = As[(mb + g + 8) * LDA + k0 + t];
                af[i][2] = As[(mb + g)     * LDA + k0 + t + 4];
                af[i][3] = As[(mb + g + 8) * LDA + k0 + t + 4];
            }
#pragma unroll
            for (int j = 0; j < 4; j++) {
                int nb = wn * 32 + j * 8;
                bf[j][0] = Bs[(nb + g) * LDA + k0 + t];
                bf[j][1] = Bs[(nb + g) * LDA + k0 + t + 4];
            }
#pragma unroll
            for (int i = 0; i < 4; i++)
#pragma unroll
                for (int j = 0; j < 4; j++)
                    mma8(acc[i][j], af[i], bf[j]);
        }
        __syncthreads();
    }

    // epilogue
    float* Cz = C + (size_t)z * M * ldc;
#pragma unroll
    for (int i = 0; i < 4; i++) {
        int r0 = bm0 + wm * 64 + i * 16 + g;
#pragma unroll
        for (int j = 0; j < 4; j++) {
            int cc = bn0 + wn * 32 + j * 8 + 2 * t;
#pragma unroll
            for (int half = 0; half < 2; half++) {
                int row = r0 + half * 8;
                float v0 = acc[i][j][half * 2 + 0];
                float v1 = acc[i][j][half * 2 + 1];
                if (cc < Nreal) {
                    if (EPI >= 1) {
                        v0 = silu_f(v0 + bias[cc]);
                        v1 = (cc + 1 < Nreal) ? silu_f(v1 + bias[cc + 1]) : 0.0f;
                    }
                    if (EPI == 2) {
                        const float* xr = xe + (size_t)(row / 3) * 128;
                        v0 *= xr[cc];
                        if (cc + 1 < Nreal) v1 *= xr[cc + 1];
                    }
                    float* cp = Cz + (size_t)row * ldc + cc;
                    if (cc + 1 < Nreal) { float2 fv = make_float2(v0, v1); *(float2*)cp = fv; }
                    else cp[0] = v0;
                }
            }
        }
    }
}

// combine split-K partials: out = epi(sum_z part[z] + bias)
template<int EPI>
__global__ void k_combine(const float* __restrict__ part, const float* __restrict__ bias,
                          const float* __restrict__ xe, float* __restrict__ outp,
                          int M, int nsplit)
{
    int idx = blockIdx.x * 256 + threadIdx.x;
    if (idx >= M * 128) return;
    int m = idx >> 7, n = idx & 127;
    float s = bias[n];
    for (int zz = 0; zz < nsplit; zz++) s += part[(size_t)zz * M * 128 + idx];
    s = silu_f(s);
    if (EPI == 2) s *= xe[(size_t)(m / 3) * 128 + n];
    outp[idx] = s;
}

// transpose: dst[c*ldD + r] = src[r*C+c] (zero-pad rows r>=R up to ldD)
__global__ void k_transpose(const float* __restrict__ src, float* __restrict__ dst,
                            int R, int C, int ldD)
{
    __shared__ float smt[32][33];
    int c0 = blockIdx.x * 32, r0 = blockIdx.y * 32;
    int tx = threadIdx.x & 31, ty = threadIdx.x >> 5;
#pragma unroll
    for (int i = 0; i < 4; i++) {
        int r = r0 + ty + i * 8, c = c0 + tx;
        smt[ty + i * 8][tx] = (r < R && c < C) ? src[(size_t)r * C + c] : 0.0f;
    }
    __syncthreads();
#pragma unroll
    for (int i = 0; i < 4; i++) {
        int c = c0 + ty + i * 8, r = r0 + tx;
        if (c < C && r < ldD) dst[(size_t)c * ldD + r] = smt[tx][ty + i * 8];
    }
}

// ---------------------------------------------------------------------------
// per-edge kernels (proven round 1; xm/ym stride 64, zero-padded)
// ---------------------------------------------------------------------------
__global__ void k_xmym(const float* __restrict__ x, const int* __restrict__ eidx,
                       float* __restrict__ xm, float* __restrict__ ym)
{
    int e = blockIdx.x, tid = threadIdx.x;
    int lane = tid & 31, warp = tid >> 5;
    int src = eidx[e], dst = eidx[NEDGE + e];
    const float* ps = x + (size_t)src * XLC;
    const float* pt = x + (size_t)dst * XLC;
    if (tid >= 49 && tid < 64) { xm[e * KCG + tid] = 0.f; ym[e * KCG + tid] = 0.f; }
    for (int l = warp; l < LF; l += 4) {
        const float* a = ps + l * 128;
        const float* b = pt + l * 128;
        float s = a[lane] + a[lane + 32] + a[lane + 64] + a[lane + 96];
        float u = b[lane] + b[lane + 32] + b[lane + 64] + b[lane + 96];
#pragma unroll
        for (int o = 16; o > 0; o >>= 1) {
            s += __shfl_xor_sync(0xffffffffu, s, o);
            u += __shfl_xor_sync(0xffffffffu, u, o);
        }
        if (lane == 0) {
            xm[e * KCG + l] = s * (1.0f / 128.0f);
            ym[e * KCG + l] = u * (1.0f / 128.0f);
        }
    }
}

__global__ void k_mid(const float* __restrict__ ym, const float* __restrict__ t,
                      float* __restrict__ mid)
{
    int e = blockIdx.x, tid = threadIdx.x;
    __shared__ float ys[LF];
    if (tid < LF) ys[tid] = ym[e * KCG + tid];
    __syncthreads();
    if (tid < MMID) {
        const float* tp = t + (size_t)e * TPAD + tid;
        float s = 0.0f;
#pragma unroll
        for (int j = 0; j < LF; j++) s = fmaf(ys[j], tp[j * MMID], s);
        mid[e * MMID + tid] = s;
    }
}

template<int ACC>
__global__ void k_contract(const float* __restrict__ mid, const float* __restrict__ t,
                           float* __restrict__ Aout)
{
    int e = blockIdx.x, tid = threadIdx.x;
    __shared__ float ms[MMID];
    if (tid < MMID) ms[tid] = mid[e * MMID + tid];
    __syncthreads();
    if (tid < LF) {
        const float* tp = t + (size_t)e * TPAD + tid;
        float s = ACC ? Aout[e * LF + tid] : 0.0f;
#pragma unroll
        for (int j = 0; j < MMID; j++) s = fmaf(ms[j], tp[j * LF], s);
        Aout[e * LF + tid] = s;
    }
}

__global__ void k_feat(const float* __restrict__ x, const float* __restrict__ glovec,
                       const float* __restrict__ wign, const int* __restrict__ eidx,
                       int node_off, int other_off, float* __restrict__ feat)
{
    int e = blockIdx.x, tid = threadIdx.x;
    __shared__ float wigS[256];
    __shared__ float gS[16];
    __shared__ float red[4];
    int node  = eidx[node_off  + e];
    int other = eidx[other_off + e];
    wigS[tid]       = wign[e * 256 + tid];
    wigS[tid + 128] = wign[e * 256 + 128 + tid];
    if (tid < 16) gS[tid] = glovec[other * LR + tid];
    __syncthreads();

    float xr[16];
    const float* xp = x + (size_t)node * XLC;
#pragma unroll
    for (int j = 0; j < 16; j++) xr[j] = xp[j * 128 + tid];

    float* fp = feat + (size_t)e * FEATW;
    for (int i = 0; i < 16; i++) {
        float a = 0.0f;
#pragma unroll
        for (int j = 0; j < 16; j++) a = fmaf(wigS[j * 16 + i], xr[j], a);
        fp[i * 129 + tid] = a;
        float s = a;
#pragma unroll
        for (int o = 16; o > 0; o >>= 1) s += __shfl_xor_sync(0xffffffffu, s, o);
        if ((tid & 31) == 0) red[tid >> 5] = s;
        __syncthreads();
        if (tid == 0)
            fp[i * 129 + 128] = (red[0] + red[1] + red[2] + red[3]) * (1.0f / 128.0f) * gS[i];
        __syncthreads();
    }
}

template<int ACC>
__global__ void k_sh(const float* __restrict__ wign, const float* __restrict__ h2,
                     float* __restrict__ sh)
{
    int e = blockIdx.x, tid = threadIdx.x;
    __shared__ float wigS[256];
    wigS[tid]       = wign[e * 256 + tid];
    wigS[tid + 128] = wign[e * 256 + 128 + tid];
    __syncthreads();
    float hr[16];
    const float* hp = h2 + (size_t)e * MSGW;
#pragma unroll
    for (int j = 0; j < 16; j++) hr[j] = hp[j * 128 + tid];
    float* sp = sh + (size_t)e * MSGW;
#pragma unroll
    for (int i = 0; i < 16; i++) {
        float s = 0.0f;
#pragma unroll
        for (int j = 0; j < 16; j++) s = fmaf(wigS[i * 16 + j], hr[j], s);
        if (ACC) sp[i * 128 + tid] += s; else sp[i * 128 + tid] = s;
    }
}

__global__ __launch_bounds__(256)
void k_rotmsg(const float* __restrict__ x, const int* __restrict__ eidx,
              const float* __restrict__ Aarr, const float* __restrict__ sh,
              const float* __restrict__ wigner, float* __restrict__ msg)
{
    int e = blockIdx.x, tid = threadIdx.x;
    __shared__ float zs[LF * 128];
    __shared__ float wgS[48 * 49];
    int src = eidx[e], dst = eidx[NEDGE + e];
    const float* xs = x + (size_t)src * XLC;
    const float* xt = x + (size_t)dst * XLC;
    const float* shp = sh + (size_t)e * MSGW;
    const float* Ap  = Aarr + e * LF;
    for (int idx = tid; idx < LF * 128; idx += 256) {
        int l = idx >> 7, c = idx & 127;
        float v = 2.0f * (xs[idx] + xt[idx]) + Ap[l];
        if (l < 16) v += shp[l * 128 + c];
        zs[idx] = v;
    }
    const float* wp = wigner + (size_t)e * (48 * 49);
    for (int idx = tid; idx < 48 * 49; idx += 256) wgS[idx] = wp[idx];
    __syncthreads();

    int cg = tid & 63, grp = tid >> 6;
    float2 acc[12];
#pragma unroll
    for (int rr = 0; rr < 12; rr++) { acc[rr].x = 0.0f; acc[rr].y = 0.0f; }
    const float2* z2 = (const float2*)zs;
    for (int l = 0; l < LF; l++) {
        float2 zv = z2[l * 64 + cg];
#pragma unroll
        for (int rr = 0; rr < 12; rr++) {
            float w = wgS[(grp * 12 + rr) * LF + l];
            acc[rr].x = fmaf(w, zv.x, acc[rr].x);
            acc[rr].y = fmaf(w, zv.y, acc[rr].y);
        }
    }
    float* mp = msg + (size_t)e * (NYR * MSGW);
#pragma unroll
    for (int rr = 0; rr < 12; rr++) {
        int row = grp * 12 + rr;
        ((float2*)(mp + row * 128))[cg] = acc[rr];
    }
}

__global__ __launch_bounds__(256)
void k_out(const float* __restrict__ m2, const float* __restrict__ winv,
           float* __restrict__ out)
{
    int e = blockIdx.x, tid = threadIdx.x;
    __shared__ float mmS[16 * 128];
    __shared__ float wvS[LF * 16];
    const float* mp = m2 + (size_t)e * (NYR * MSGW);
    for (int idx = tid; idx < 2048; idx += 256)
        mmS[idx] = (mp[idx] + mp[idx + 2048] + mp[idx + 4096]) * (1.0f / 3.0f);
    const float* wp = winv + (size_t)e * (LF * 16);
    for (int idx = tid; idx < LF * 16; idx += 256) wvS[idx] = wp[idx];
    __syncthreads();

    const float INV3 = 0.5773502691896258f;
    int cg = tid & 63, grp = tid >> 6;
    const float2* mm2 = (const float2*)mmS;
    float* op = out + (size_t)e * XLC;
    for (int b = grp; b < LF; b += 4) {
        float2 s; s.x = 0.0f; s.y = 0.0f;
#pragma unroll
        for (int r = 0; r < 16; r++) {
            float w = wvS[b * 16 + r];
            float2 mv = mm2[r * 64 + cg];
            s.x = fmaf(w, mv.x, s.x);
            s.y = fmaf(w, mv.y, s.y);
        }
        s.x *= INV3; s.y *= INV3;
        ((float2*)(op + b * 128))[cg] = s;
    }
}

// ---------------------------------------------------------------------------
extern "C" void kernel_launch(void* const* d_in, const int* in_sizes, int n_in,
                              void* d_out, int out_size)
{
    const float* x      = (const float*)d_in[0];
    const float* glovec = (const float*)d_in[2];
    const float* x_edge = (const float*)d_in[3];
    const int*   eidx   = (const int*)  d_in[4];
    const float* W_cg1  = (const float*)d_in[8];
    const float* W_cg21 = (const float*)d_in[9];
    const float* W_cg22 = (const float*)d_in[10];
    const float* Wn1a   = (const float*)d_in[11];
    const float* bn1a   = (const float*)d_in[12];
    const float* Wn1b   = (const float*)d_in[13];
    const float* bn1b   = (const float*)d_in[14];
    const float* Wn2a   = (const float*)d_in[15];
    const float* bn2a   = (const float*)d_in[16];
    const float* Wn2b   = (const float*)d_in[17];
    const float* bn2b   = (const float*)d_in[18];
    const float* Wd     = (const float*)d_in[19];
    const float* bd     = (const float*)d_in[20];
    const float* Wp1    = (const float*)d_in[21];
    const float* bp1    = (const float*)d_in[22];
    const float* Wp2    = (const float*)d_in[23];
    const float* bp2    = (const float*)d_in[24];
    const float* wigner = (const float*)d_in[25];
    const float* winv   = (const float*)d_in[26];
    const float* wign   = (const float*)d_in[27];
    float* out = (float*)d_out;

    float *pWdT, *pW1aT, *pW1bT, *pW2aT, *pW2bT, *pWp1T, *pWp2T, *pWc1T, *pWc2T, *pWc3T;
    float *p_xe, *p_xm, *p_ym, *p_t, *p_mid, *p_A, *p_feat, *p_h, *p_h2,
          *p_sh, *p_msg, *p_m1, *p_m2, *p_part;
    cudaGetSymbolAddress((void**)&pWdT,  g_WdT);
    cudaGetSymbolAddress((void**)&pW1aT, g_Wn1aT);
    cudaGetSymbolAddress((void**)&pW1bT, g_Wn1bT);
    cudaGetSymbolAddress((void**)&pW2aT, g_Wn2aT);
    cudaGetSymbolAddress((void**)&pW2bT, g_Wn2bT);
    cudaGetSymbolAddress((void**)&pWp1T, g_Wp1T);
    cudaGetSymbolAddress((void**)&pWp2T, g_Wp2T);
    cudaGetSymbolAddress((void**)&pWc1T, g_Wc1T);
    cudaGetSymbolAddress((void**)&pWc2T, g_Wc2T);
    cudaGetSymbolAddress((void**)&pWc3T, g_Wc3T);
    cudaGetSymbolAddress((void**)&p_xe,   g_xe);
    cudaGetSymbolAddress((void**)&p_xm,   g_xm);
    cudaGetSymbolAddress((void**)&p_ym,   g_ym);
    cudaGetSymbolAddress((void**)&p_t,    g_t);
    cudaGetSymbolAddress((void**)&p_mid,  g_mid);
    cudaGetSymbolAddress((void**)&p_A,    g_A);
    cudaGetSymbolAddress((void**)&p_feat, g_feat);
    cudaGetSymbolAddress((void**)&p_h,    g_h);
    cudaGetSymbolAddress((void**)&p_h2,   g_h2);
    cudaGetSymbolAddress((void**)&p_sh,   g_sh);
    cudaGetSymbolAddress((void**)&p_msg,  g_msg);
    cudaGetSymbolAddress((void**)&p_m1,   g_m1);
    cudaGetSymbolAddress((void**)&p_m2,   g_m2);
    cudaGetSymbolAddress((void**)&p_part, g_part);

    cudaFuncSetAttribute(tgemm<0>, cudaFuncAttributeMaxDynamicSharedMemorySize, DYN_SMEM);
    cudaFuncSetAttribute(tgemm<1>, cudaFuncAttributeMaxDynamicSharedMemorySize, DYN_SMEM);
    cudaFuncSetAttribute(tgemm<2>, cudaFuncAttributeMaxDynamicSharedMemorySize, DYN_SMEM);

    auto tgrid = [](int R, int C, int ldD) {
        return dim3((C + 31) / 32, (ldD + 31) / 32);
    };

    // ---- weight transposes ([K,N] -> [N,K]) ----
    k_transpose<<<tgrid(128, 128, 128),   256>>>(Wd,   pWdT,  128, 128, 128);
    k_transpose<<<tgrid(FEATW, 128, FEATW), 256>>>(Wn1a, pW1aT, FEATW, 128, FEATW);
    k_transpose<<<tgrid(128, 2048, 128),  256>>>(Wn1b, pW1bT, 128, 2048, 128);
    k_transpose<<<tgrid(FEATW, 128, FEATW), 256>>>(Wn2a, pW2aT, FEATW, 128, FEATW);
    k_transpose<<<tgrid(128, 2048, 128),  256>>>(Wn2b, pW2bT, 128, 2048, 128);
    k_transpose<<<tgrid(2048, 128, 2048), 256>>>(Wp1,  pWp1T, 2048, 128, 2048);
    k_transpose<<<tgrid(128, 2048, 128),  256>>>(Wp2,  pWp2T, 128, 2048, 128);
    k_transpose<<<tgrid(49, 1225, KCG),   256>>>(W_cg1,  pWc1T, 49, 1225, KCG);
    k_transpose<<<tgrid(49, 1225, KCG),   256>>>(W_cg21, pWc2T, 49, 1225, KCG);
    k_transpose<<<tgrid(49, 1225, KCG),   256>>>(W_cg22, pWc3T, 49, 1225, KCG);

    // 1. xe = silu(x_edge @ Wd + bd)
    tgemm<1><<<dim3(1, 32, 1), 256, DYN_SMEM>>>(x_edge, pWdT, bd, nullptr, p_xe,
                                                NEDGE, 128, 128, 128, 4, 4);

    // 2. channel means (K padded to 64)
    k_xmym<<<NEDGE, 128>>>(x, eidx, p_xm, p_ym);

    // 3. CG bilinears: [4096,64] x [1225,64]^T
    tgemm<0><<<dim3(10, 32, 1), 256, DYN_SMEM>>>(p_xm, pWc1T, nullptr, nullptr, p_t,
                                                 NEDGE, 1225, KCG, TPAD, 2, 2);
    k_mid<<<NEDGE, 64>>>(p_ym, p_t, p_mid);
    tgemm<0><<<dim3(10, 32, 1), 256, DYN_SMEM>>>(p_xm, pWc2T, nullptr, nullptr, p_t,
                                                 NEDGE, 1225, KCG, TPAD, 2, 2);
    k_contract<0><<<NEDGE, 64>>>(p_mid, p_t, p_A);
    tgemm<0><<<dim3(10, 32, 1), 256, DYN_SMEM>>>(p_ym, pWc3T, nullptr, nullptr, p_t,
                                                 NEDGE, 1225, KCG, TPAD, 2, 2);
    k_contract<1><<<NEDGE, 64>>>(p_mid, p_t, p_A);

    // 4. node_interaction 1: feat @ Wn1a (K=2064, split-4), then @ Wn1b
    k_feat<<<NEDGE, 128>>>(x, glovec, wign, eidx, 0, NEDGE, p_feat);
    tgemm<0><<<dim3(1, 32, 4), 256, DYN_SMEM>>>(p_feat, pW1aT, nullptr, nullptr, p_part,
                                                NEDGE, 128, FEATW, 128, 65, 17);
    k_combine<1><<<(NEDGE * 128 + 255) / 256, 256>>>(p_part, bn1a, nullptr, p_h, NEDGE, 4);
    tgemm<1><<<dim3(16, 32, 1), 256, DYN_SMEM>>>(p_h, pW1bT, bn1b, nullptr, p_h2,
                                                 NEDGE, 2048, 128, 2048, 4, 4);
    k_sh<0><<<NEDGE, 128>>>(wign, p_h2, p_sh);

    // 5. node_interaction 2
    k_feat<<<NEDGE, 128>>>(x, glovec, wign, eidx, NEDGE, 0, p_feat);
    tgemm<0><<<dim3(1, 32, 4), 256, DYN_SMEM>>>(p_feat, pW2aT, nullptr, nullptr, p_part,
                                                NEDGE, 128, FEATW, 128, 65, 17);
    k_combine<1><<<(NEDGE * 128 + 255) / 256, 256>>>(p_part, bn2a, nullptr, p_h, NEDGE, 4);
    tgemm<1><<<dim3(16, 32, 1), 256, DYN_SMEM>>>(p_h, pW2bT, bn2b, nullptr, p_h2,
                                                 NEDGE, 2048, 128, 2048, 4, 4);
    k_sh<1><<<NEDGE, 128>>>(wign, p_h2, p_sh);

    // 6. fused z-build + rotate
    k_rotmsg<<<NEDGE, 256>>>(x, eidx, p_A, p_sh, wigner, p_msg);

    // 7. edge MLP: msg @ Wp1 (K=2048, split-2) + xe epilogue, then @ Wp2
    tgemm<0><<<dim3(1, 96, 2), 256, DYN_SMEM>>>(p_msg, pWp1T, nullptr, nullptr, p_part,
                                                NEDGE * NYR, 128, 2048, 128, 64, 32);
    k_combine<2><<<(NEDGE * NYR * 128 + 255) / 256, 256>>>(p_part, bp1, p_xe, p_m1,
                                                           NEDGE * NYR, 2);
    tgemm<1><<<dim3(16, 96, 1), 256, DYN_SMEM>>>(p_m1, pWp2T, bp2, nullptr, p_m2,
                                                 NEDGE * NYR, 2048, 128, 2048, 4, 4);

    // 8. NY-mean + inverse rotation
    k_out<<<NEDGE, 256>>>(p_m2, winv, out);
}

// round 6
// speedup vs baseline: 2.8915x; 1.1641x over previous
#include <cuda_runtime.h>
#include <cstdint>
#include <math.h>

// ---------------- problem constants ----------------
#define NNODE 2048
#define NEDGE 4096
#define LF    49
#define LR    16
#define MMID  25
#define NYR   3
#define CCH   128
#define HID   128
#define XLC   (LF*CCH)      // 6272
#define FEATW 2064          // 16*129
#define MSGW  2048          // 16*128
#define TPAD  1280          // padded 1225
#define KCG   64            // padded 49

// ---------------- device scratch ----------------
__device__ __align__(16) float g_WdT  [128*128];
__device__ __align__(16) float g_Wn1aT[128*FEATW];
__device__ __align__(16) float g_Wn1bT[2048*128];
__device__ __align__(16) float g_Wn2aT[128*FEATW];
__device__ __align__(16) float g_Wn2bT[2048*128];
__device__ __align__(16) float g_Wp1T [128*2048];
__device__ __align__(16) float g_Wp2T [2048*128];
__device__ __align__(16) float g_Wc1T [TPAD*KCG];
__device__ __align__(16) float g_Wc2T [TPAD*KCG];
__device__ __align__(16) float g_Wc3T [TPAD*KCG];
__device__ __align__(16) float g_xe   [NEDGE*HID];
__device__ __align__(16) float g_xm   [NEDGE*KCG];
__device__ __align__(16) float g_ym   [NEDGE*KCG];
__device__ __align__(16) float g_t3   [3*NEDGE*TPAD];
__device__ __align__(16) float g_mid  [NEDGE*MMID];
__device__ __align__(16) float g_A    [NEDGE*LF];
__device__ __align__(16) float g_feat [2*NEDGE*FEATW];
__device__ __align__(16) float g_h    [2*NEDGE*HID];
__device__ __align__(16) float g_h2   [2*NEDGE*MSGW];
__device__ __align__(16) float g_sh   [NEDGE*LR*CCH];
__device__ __align__(16) float g_msg  [NEDGE*NYR*MSGW];
__device__ __align__(16) float g_m1   [NEDGE*NYR*HID];
__device__ __align__(16) float g_m2   [NEDGE*NYR*MSGW];
__device__ __align__(16) float g_part [4*12288*128];

__device__ __forceinline__ float silu_f(float v) { return v / (1.0f + __expf(-v)); }

__device__ __forceinline__ uint32_t f2tf32(float f) {
    uint32_t r;
    asm("cvt.rna.tf32.f32 %0, %1;" : "=r"(r) : "f"(f));
    return r;
}

__device__ __forceinline__ void mma8(float* d, const uint32_t* a, const uint32_t* b) {
    asm volatile(
        "mma.sync.aligned.m16n8k8.row.col.f32.tf32.tf32.f32 "
        "{%0,%1,%2,%3}, {%4,%5,%6,%7}, {%8,%9}, {%0,%1,%2,%3};"
        : "+f"(d[0]), "+f"(d[1]), "+f"(d[2]), "+f"(d[3])
        : "r"(a[0]), "r"(a[1]), "r"(a[2]), "r"(a[3]), "r"(b[0]), "r"(b[1]));
}

// ---------------------------------------------------------------------------
// tf32 mma.sync GEMM: C[M,N] = A[M,K] @ BT[N,K]^T   (row-major A, BT)
// CTA tile 128x128, K chunks of 32, 8 warps (2x4), warp tile 64x32.
// zmode=0: grid.z = split-K; z handles chunks [z*cpz..), writes C + z*M*ldc.
//          B/bias selected by blockIdx.y < ysplit ? (B0,bias0) : (B1,bias1).
// zmode=1: grid.z = batch; A/B selected by z, C += z*M*ldc, all chunks.
// EPI: 0=raw, 1=bias+silu, 2=bias+silu then *= xe[(row/3)*128+col]
// Requires M%128==0, K%4==0.
// ---------------------------------------------------------------------------
#define LDA 36
#define ATILE (128*LDA)
#define BUFSZ (2*ATILE)
#define DYN_SMEM (2*BUFSZ*4)     // 73728 bytes

template<int EPI>
__global__ __launch_bounds__(256, 1)
void tgemm(const float* __restrict__ A0, const float* __restrict__ A1,
           const float* __restrict__ A2,
           const float* __restrict__ B0, const float* __restrict__ B1,
           const float* __restrict__ B2,
           const float* __restrict__ bias0, const float* __restrict__ bias1,
           const float* __restrict__ xe,
           float* __restrict__ C, int M, int Nreal, int K, int ldc,
           int chunksTotal, int chunksPerZ, int zmode, int ysplit)
{
    extern __shared__ uint32_t sm[];
    const int tid  = threadIdx.x;
    const int lane = tid & 31;
    const int warp = tid >> 5;
    const int wm = warp >> 2, wn = warp & 3;
    const int g = lane >> 2, t = lane & 3;

    const int bm0 = blockIdx.y * 128;
    const int bn0 = blockIdx.x * 128;
    const int z   = blockIdx.z;

    const float* A;
    const float* BT;
    const float* bias;
    int c0, cend;
    if (zmode) {
        A    = (z == 0) ? A0 : (z == 1) ? A1 : A2;
        BT   = (z == 0) ? B0 : (z == 1) ? B1 : B2;
        bias = bias0;
        c0 = 0; cend = chunksTotal;
    } else {
        A    = A0;
        BT   = ((int)blockIdx.y < ysplit) ? B0 : B1;
        bias = ((int)blockIdx.y < ysplit) ? bias0 : bias1;
        c0 = z * chunksPerZ;
        cend = c0 + chunksPerZ; if (cend > chunksTotal) cend = chunksTotal;
    }

    float acc[4][4][4];
#pragma unroll
    for (int i = 0; i < 4; i++)
#pragma unroll
        for (int j = 0; j < 4; j++)
#pragma unroll
            for (int q = 0; q < 4; q++) acc[i][j][q] = 0.0f;

    float4 pa[4], pb[4];

    auto loadRegs = [&](int c) {
        const int kbase = c * 32;
#pragma unroll
        for (int i = 0; i < 4; i++) {
            int idx = tid + i * 256;
            int r = idx >> 3, seg = idx & 7;
            int gk = kbase + seg * 4;
            float4 v = make_float4(0.f, 0.f, 0.f, 0.f);
            if (gk < K) v = *(const float4*)(A + (size_t)(bm0 + r) * K + gk);
            pa[i] = v;
        }
#pragma unroll
        for (int i = 0; i < 4; i++) {
            int idx = tid + i * 256;
            int r = idx >> 3, seg = idx & 7;
            int gn = bn0 + r, gk = kbase + seg * 4;
            float4 v = make_float4(0.f, 0.f, 0.f, 0.f);
            if (gn < Nreal && gk < K) v = *(const float4*)(BT + (size_t)gn * K + gk);
            pb[i] = v;
        }
    };

    auto storeRegs = [&](int b) {
        uint32_t* As = sm + b * BUFSZ;
        uint32_t* Bs = As + ATILE;
#pragma unroll
        for (int i = 0; i < 4; i++) {
            int idx = tid + i * 256;
            int r = idx >> 3, seg = idx & 7;
            uint32_t* p = As + r * LDA + seg * 4;
            p[0] = f2tf32(pa[i].x); p[1] = f2tf32(pa[i].y);
            p[2] = f2tf32(pa[i].z); p[3] = f2tf32(pa[i].w);
        }
#pragma unroll
        for (int i = 0; i < 4; i++) {
            int idx = tid + i * 256;
            int r = idx >> 3, seg = idx & 7;
            uint32_t* p = Bs + r * LDA + seg * 4;
            p[0] = f2tf32(pb[i].x); p[1] = f2tf32(pb[i].y);
            p[2] = f2tf32(pb[i].z); p[3] = f2tf32(pb[i].w);
        }
    };

    loadRegs(c0);
    for (int c = c0; c < cend; ++c) {
        int b = (c - c0) & 1;
        storeRegs(b);
        __syncthreads();
        if (c + 1 < cend) loadRegs(c + 1);

        const uint32_t* As = sm + b * BUFSZ;
        const uint32_t* Bs = As + ATILE;
#pragma unroll
        for (int kk = 0; kk < 4; kk++) {
            const int k0 = kk * 8;
            uint32_t af[4][4], bf[4][2];
#pragma unroll
            for (int i = 0; i < 4; i++) {
                int mb = wm * 64 + i * 16;
                af[i][0] = As[(mb + g)     * LDA + k0 + t];
                af[i][1] = As[(mb + g + 8) * LDA + k0 + t];
                af[i][2] = As[(mb + g)     * LDA + k0 + t + 4];
                af[i][3] = As[(mb + g + 8) * LDA + k0 + t + 4];
            }
#pragma unroll
            for (int j = 0; j < 4; j++) {
                int nb = wn * 32 + j * 8;
                bf[j][0] = Bs[(nb + g) * LDA + k0 + t];
                bf[j][1] = Bs[(nb + g) * LDA + k0 + t + 4];
            }
#pragma unroll
            for (int i = 0; i < 4; i++)
#pragma unroll
                for (int j = 0; j < 4; j++)
                    mma8(acc[i][j], af[i], bf[j]);
        }
        // NOTE: single barrier per chunk. Buffer b is not re-written until the
        // next-next iteration's storeRegs, which every warp reaches only after
        // passing the next iteration's barrier (post its own mma on b). Safe.
    }

    float* Cz = C + (size_t)z * M * ldc;
#pragma unroll
    for (int i = 0; i < 4; i++) {
        int r0 = bm0 + wm * 64 + i * 16 + g;
#pragma unroll
        for (int j = 0; j < 4; j++) {
            int cc = bn0 + wn * 32 + j * 8 + 2 * t;
#pragma unroll
            for (int half = 0; half < 2; half++) {
                int row = r0 + half * 8;
                float v0 = acc[i][j][half * 2 + 0];
                float v1 = acc[i][j][half * 2 + 1];
                if (cc < Nreal) {
                    if (EPI >= 1) {
                        v0 = silu_f(v0 + bias[cc]);
                        v1 = (cc + 1 < Nreal) ? silu_f(v1 + bias[cc + 1]) : 0.0f;
                    }
                    if (EPI == 2) {
                        const float* xr = xe + (size_t)(row / 3) * 128;
                        v0 *= xr[cc];
                        if (cc + 1 < Nreal) v1 *= xr[cc + 1];
                    }
                    float* cp = Cz + (size_t)row * ldc + cc;
                    if (cc + 1 < Nreal) { float2 fv = make_float2(v0, v1); *(float2*)cp = fv; }
                    else cp[0] = v0;
                }
            }
        }
    }
}

// combine split-K partials: out = epi(sum_z part[z] + bias); bias1 for rows>=Mhalf
template<int EPI>
__global__ void k_combine(const float* __restrict__ part, const float* __restrict__ bias0,
                          const float* __restrict__ bias1, const float* __restrict__ xe,
                          float* __restrict__ outp, int M, int nsplit, int Mhalf)
{
    int idx = blockIdx.x * 256 + threadIdx.x;
    if (idx >= M * 128) return;
    int m = idx >> 7, n = idx & 127;
    float s = (m < Mhalf) ? bias0[n] : bias1[n];
    for (int zz = 0; zz < nsplit; zz++) s += part[(size_t)zz * M * 128 + idx];
    s = silu_f(s);
    if (EPI == 2) s *= xe[(size_t)(m / 3) * 128 + n];
    outp[idx] = s;
}

// ---------------- fused multi-transpose (one launch for all weights) --------
struct TD { const float* src; float* dst; int R, C, ldD, tilesX, tileOff; };
struct TDPack { TD d[10]; };

__global__ void k_tmulti(TDPack P, int ndesc)
{
    __shared__ float smt[32][33];
    int bid = blockIdx.x;
    int di = 0;
    for (int i = 1; i < ndesc; i++) if (bid >= P.d[i].tileOff) di = i;
    const TD& D = P.d[di];
    int ti = bid - D.tileOff;
    int c0 = (ti % D.tilesX) * 32;
    int r0 = (ti / D.tilesX) * 32;
    int tx = threadIdx.x & 31, ty = threadIdx.x >> 5;
#pragma unroll
    for (int i = 0; i < 4; i++) {
        int r = r0 + ty + i * 8, c = c0 + tx;
        smt[ty + i * 8][tx] = (r < D.R && c < D.C) ? D.src[(size_t)r * D.C + c] : 0.0f;
    }
    __syncthreads();
#pragma unroll
    for (int i = 0; i < 4; i++) {
        int c = c0 + ty + i * 8, r = r0 + tx;
        if (c < D.C && r < D.ldD) D.dst[(size_t)c * D.ldD + r] = smt[tx][ty + i * 8];
    }
}

// ---------------------------------------------------------------------------
// per-edge kernels
// ---------------------------------------------------------------------------
__global__ void k_xmym(const float* __restrict__ x, const int* __restrict__ eidx,
                       float* __restrict__ xm, float* __restrict__ ym)
{
    int e = blockIdx.x, tid = threadIdx.x;
    int lane = tid & 31, warp = tid >> 5;
    int src = eidx[e], dst = eidx[NEDGE + e];
    const float* ps = x + (size_t)src * XLC;
    const float* pt = x + (size_t)dst * XLC;
    if (tid >= 49 && tid < 64) { xm[e * KCG + tid] = 0.f; ym[e * KCG + tid] = 0.f; }
    for (int l = warp; l < LF; l += 4) {
        const float* a = ps + l * 128;
        const float* b = pt + l * 128;
        float s = a[lane] + a[lane + 32] + a[lane + 64] + a[lane + 96];
        float u = b[lane] + b[lane + 32] + b[lane + 64] + b[lane + 96];
#pragma unroll
        for (int o = 16; o > 0; o >>= 1) {
            s += __shfl_xor_sync(0xffffffffu, s, o);
            u += __shfl_xor_sync(0xffffffffu, u, o);
        }
        if (lane == 0) {
            xm[e * KCG + l] = s * (1.0f / 128.0f);
            ym[e * KCG + l] = u * (1.0f / 128.0f);
        }
    }
}

__global__ void k_mid(const float* __restrict__ ym, const float* __restrict__ t,
                      float* __restrict__ mid)
{
    int e = blockIdx.x, tid = threadIdx.x;
    __shared__ float ys[LF];
    if (tid < LF) ys[tid] = ym[e * KCG + tid];
    __syncthreads();
    if (tid < MMID) {
        const float* tp = t + (size_t)e * TPAD + tid;
        float s = 0.0f;
#pragma unroll
        for (int j = 0; j < LF; j++) s = fmaf(ys[j], tp[j * MMID], s);
        mid[e * MMID + tid] = s;
    }
}

// A[e,o] = sum_j mid[e,j] * (t1 + t2)[e, j*49 + o]
__global__ void k_contract2(const float* __restrict__ mid, const float* __restrict__ t1,
                            const float* __restrict__ t2, float* __restrict__ Aout)
{
    int e = blockIdx.x, tid = threadIdx.x;
    __shared__ float ms[MMID];
    if (tid < MMID) ms[tid] = mid[e * MMID + tid];
    __syncthreads();
    if (tid < LF) {
        const float* tp1 = t1 + (size_t)e * TPAD + tid;
        const float* tp2 = t2 + (size_t)e * TPAD + tid;
        float s = 0.0f;
#pragma unroll
        for (int j = 0; j < MMID; j++)
            s = fmaf(ms[j], tp1[j * LF] + tp2[j * LF], s);
        Aout[e * LF + tid] = s;
    }
}

// batched: blocks 0..4095 -> (node=src, other=dst); 4096..8191 -> swapped
__global__ void k_feat(const float* __restrict__ x, const float* __restrict__ glovec,
                       const float* __restrict__ wign, const int* __restrict__ eidx,
                       float* __restrict__ feat)
{
    int e2 = blockIdx.x, tid = threadIdx.x;
    int half = e2 >> 12;
    int e = e2 & 4095;
    __shared__ float wigS[256];
    __shared__ float gS[16];
    __shared__ float red[4];
    int node  = eidx[half ? (NEDGE + e) : e];
    int other = eidx[half ? e : (NEDGE + e)];
    wigS[tid]       = wign[e * 256 + tid];
    wigS[tid + 128] = wign[e * 256 + 128 + tid];
    if (tid < 16) gS[tid] = glovec[other * LR + tid];
    __syncthreads();

    float xr[16];
    const float* xp = x + (size_t)node * XLC;
#pragma unroll
    for (int j = 0; j < 16; j++) xr[j] = xp[j * 128 + tid];

    float* fp = feat + (size_t)e2 * FEATW;
    for (int i = 0; i < 16; i++) {
        float a = 0.0f;
#pragma unroll
        for (int j = 0; j < 16; j++) a = fmaf(wigS[j * 16 + i], xr[j], a);
        fp[i * 129 + tid] = a;
        float s = a;
#pragma unroll
        for (int o = 16; o > 0; o >>= 1) s += __shfl_xor_sync(0xffffffffu, s, o);
        if ((tid & 31) == 0) red[tid >> 5] = s;
        __syncthreads();
        if (tid == 0)
            fp[i * 129 + 128] = (red[0] + red[1] + red[2] + red[3]) * (1.0f / 128.0f) * gS[i];
        __syncthreads();
    }
}

// sh[e] = wig_node[e] @ (h2[e] + h2[e+4096])  -- both halves in one pass
__global__ void k_sh2(const float* __restrict__ wign, const float* __restrict__ h2,
                      float* __restrict__ sh)
{
    int e = blockIdx.x, tid = threadIdx.x;
    __shared__ float wigS[256];
    wigS[tid]       = wign[e * 256 + tid];
    wigS[tid + 128] = wign[e * 256 + 128 + tid];
    __syncthreads();
    float hr[16];
    const float* hpa = h2 + (size_t)e * MSGW;
    const float* hpb = h2 + (size_t)(e + NEDGE) * MSGW;
#pragma unroll
    for (int j = 0; j < 16; j++) hr[j] = hpa[j * 128 + tid] + hpb[j * 128 + tid];
    float* sp = sh + (size_t)e * MSGW;
#pragma unroll
    for (int i = 0; i < 16; i++) {
        float s = 0.0f;
#pragma unroll
        for (int j = 0; j < 16; j++) s = fmaf(wigS[i * 16 + j], hr[j], s);
        sp[i * 128 + tid] = s;
    }
}

__global__ __launch_bounds__(256)
void k_rotmsg(const float* __restrict__ x, const int* __restrict__ eidx,
              const float* __restrict__ Aarr, const float* __restrict__ sh,
              const float* __restrict__ wigner, float* __restrict__ msg)
{
    int e = blockIdx.x, tid = threadIdx.x;
    __shared__ float zs[LF * 128];
    __shared__ float wgS[48 * 49];
    __shared__ float As_[LF];
    int src = eidx[e], dst = eidx[NEDGE + e];
    const float4* xs4 = (const float4*)(x + (size_t)src * XLC);
    const float4* xt4 = (const float4*)(x + (size_t)dst * XLC);
    const float4* sh4 = (const float4*)(sh + (size_t)e * MSGW);
    if (tid < LF) As_[tid] = Aarr[e * LF + tid];
    __syncthreads();
    float4* zs4 = (float4*)zs;
    for (int i4 = tid; i4 < LF * 32; i4 += 256) {      // 1568 float4s
        int l = i4 >> 5;
        float4 a = xs4[i4], b = xt4[i4];
        float al = As_[l];
        float4 v;
        v.x = 2.0f * (a.x + b.x) + al;
        v.y = 2.0f * (a.y + b.y) + al;
        v.z = 2.0f * (a.z + b.z) + al;
        v.w = 2.0f * (a.w + b.w) + al;
        if (l < 16) {
            float4 s = sh4[i4];
            v.x += s.x; v.y += s.y; v.z += s.z; v.w += s.w;
        }
        zs4[i4] = v;
    }
    const float4* wp4 = (const float4*)(wigner + (size_t)e * (48 * 49));
    float4* wg4 = (float4*)wgS;
    for (int i4 = tid; i4 < 588; i4 += 256) wg4[i4] = wp4[i4];
    __syncthreads();

    int cg = tid & 63, grp = tid >> 6;
    float2 acc[12];
#pragma unroll
    for (int rr = 0; rr < 12; rr++) { acc[rr].x = 0.0f; acc[rr].y = 0.0f; }
    const float2* z2 = (const float2*)zs;
    for (int l = 0; l < LF; l++) {
        float2 zv = z2[l * 64 + cg];
#pragma unroll
        for (int rr = 0; rr < 12; rr++) {
            float w = wgS[(grp * 12 + rr) * LF + l];
            acc[rr].x = fmaf(w, zv.x, acc[rr].x);
            acc[rr].y = fmaf(w, zv.y, acc[rr].y);
        }
    }
    float* mp = msg + (size_t)e * (NYR * MSGW);
#pragma unroll
    for (int rr = 0; rr < 12; rr++) {
        int row = grp * 12 + rr;
        ((float2*)(mp + row * 128))[cg] = acc[rr];
    }
}

__global__ __launch_bounds__(256)
void k_out(const float* __restrict__ m2, const float* __restrict__ winv,
           float* __restrict__ out)
{
    int e = blockIdx.x, tid = threadIdx.x;
    __shared__ float mmS[16 * 128];
    __shared__ float wvS[LF * 16];
    const float4* mp4 = (const float4*)(m2 + (size_t)e * (NYR * MSGW));
    float4* mm4 = (float4*)mmS;
    for (int i4 = tid; i4 < 512; i4 += 256) {
        float4 a = mp4[i4], b = mp4[i4 + 512], c = mp4[i4 + 1024];
        float4 v;
        v.x = (a.x + b.x + c.x) * (1.0f / 3.0f);
        v.y = (a.y + b.y + c.y) * (1.0f / 3.0f);
        v.z = (a.z + b.z + c.z) * (1.0f / 3.0f);
        v.w = (a.w + b.w + c.w) * (1.0f / 3.0f);
        mm4[i4] = v;
    }
    const float4* wp4 = (const float4*)(winv + (size_t)e * (LF * 16));
    float4* wv4 = (float4*)wvS;
    for (int i4 = tid; i4 < 196; i4 += 256) wv4[i4] = wp4[i4];
    __syncthreads();

    const float INV3 = 0.5773502691896258f;
    int cg = tid & 63, grp = tid >> 6;
    const float2* mm2 = (const float2*)mmS;
    float* op = out + (size_t)e * XLC;
    for (int b = grp; b < LF; b += 4) {
        float2 s; s.x = 0.0f; s.y = 0.0f;
#pragma unroll
        for (int r = 0; r < 16; r++) {
            float w = wvS[b * 16 + r];
            float2 mv = mm2[r * 64 + cg];
            s.x = fmaf(w, mv.x, s.x);
            s.y = fmaf(w, mv.y, s.y);
        }
        s.x *= INV3; s.y *= INV3;
        ((float2*)(op + b * 128))[cg] = s;
    }
}

// ---------------------------------------------------------------------------
extern "C" void kernel_launch(void* const* d_in, const int* in_sizes, int n_in,
                              void* d_out, int out_size)
{
    const float* x      = (const float*)d_in[0];
    const float* glovec = (const float*)d_in[2];
    const float* x_edge = (const float*)d_in[3];
    const int*   eidx   = (const int*)  d_in[4];
    const float* W_cg1  = (const float*)d_in[8];
    const float* W_cg21 = (const float*)d_in[9];
    const float* W_cg22 = (const float*)d_in[10];
    const float* Wn1a   = (const float*)d_in[11];
    const float* bn1a   = (const float*)d_in[12];
    const float* Wn1b   = (const float*)d_in[13];
    const float* bn1b   = (const float*)d_in[14];
    const float* Wn2a   = (const float*)d_in[15];
    const float* bn2a   = (const float*)d_in[16];
    const float* Wn2b   = (const float*)d_in[17];
    const float* bn2b   = (const float*)d_in[18];
    const float* Wd     = (const float*)d_in[19];
    const float* bd     = (const float*)d_in[20];
    const float* Wp1    = (const float*)d_in[21];
    const float* bp1    = (const float*)d_in[22];
    const float* Wp2    = (const float*)d_in[23];
    const float* bp2    = (const float*)d_in[24];
    const float* wigner = (const float*)d_in[25];
    const float* winv   = (const float*)d_in[26];
    const float* wign   = (const float*)d_in[27];
    float* out = (float*)d_out;

    float *pWdT, *pW1aT, *pW1bT, *pW2aT, *pW2bT, *pWp1T, *pWp2T, *pWc1T, *pWc2T, *pWc3T;
    float *p_xe, *p_xm, *p_ym, *p_t3, *p_mid, *p_A, *p_feat, *p_h, *p_h2,
          *p_sh, *p_msg, *p_m1, *p_m2, *p_part;
    cudaGetSymbolAddress((void**)&pWdT,  g_WdT);
    cudaGetSymbolAddress((void**)&pW1aT, g_Wn1aT);
    cudaGetSymbolAddress((void**)&pW1bT, g_Wn1bT);
    cudaGetSymbolAddress((void**)&pW2aT, g_Wn2aT);
    cudaGetSymbolAddress((void**)&pW2bT, g_Wn2bT);
    cudaGetSymbolAddress((void**)&pWp1T, g_Wp1T);
    cudaGetSymbolAddress((void**)&pWp2T, g_Wp2T);
    cudaGetSymbolAddress((void**)&pWc1T, g_Wc1T);
    cudaGetSymbolAddress((void**)&pWc2T, g_Wc2T);
    cudaGetSymbolAddress((void**)&pWc3T, g_Wc3T);
    cudaGetSymbolAddress((void**)&p_xe,   g_xe);
    cudaGetSymbolAddress((void**)&p_xm,   g_xm);
    cudaGetSymbolAddress((void**)&p_ym,   g_ym);
    cudaGetSymbolAddress((void**)&p_t3,   g_t3);
    cudaGetSymbolAddress((void**)&p_mid,  g_mid);
    cudaGetSymbolAddress((void**)&p_A,    g_A);
    cudaGetSymbolAddress((void**)&p_feat, g_feat);
    cudaGetSymbolAddress((void**)&p_h,    g_h);
    cudaGetSymbolAddress((void**)&p_h2,   g_h2);
    cudaGetSymbolAddress((void**)&p_sh,   g_sh);
    cudaGetSymbolAddress((void**)&p_msg,  g_msg);
    cudaGetSymbolAddress((void**)&p_m1,   g_m1);
    cudaGetSymbolAddress((void**)&p_m2,   g_m2);
    cudaGetSymbolAddress((void**)&p_part, g_part);

    cudaFuncSetAttribute(tgemm<0>, cudaFuncAttributeMaxDynamicSharedMemorySize, DYN_SMEM);
    cudaFuncSetAttribute(tgemm<1>, cudaFuncAttributeMaxDynamicSharedMemorySize, DYN_SMEM);
    cudaFuncSetAttribute(tgemm<2>, cudaFuncAttributeMaxDynamicSharedMemorySize, DYN_SMEM);

    const int BIG = 1 << 30;

    // ---- all weight transposes in ONE launch ----
    {
        TDPack P;
        auto set = [&](int i, const float* s, float* dst, int R, int C, int ldD, int& off) {
            int tx = (C + 31) / 32, ty = (ldD + 31) / 32;
            P.d[i] = TD{ s, dst, R, C, ldD, tx, off };
            off += tx * ty;
        };
        int off = 0;
        set(0, Wd,    pWdT,  128,  128,  128,  off);
        set(1, Wn1a,  pW1aT, FEATW,128,  FEATW,off);
        set(2, Wn1b,  pW1bT, 128,  2048, 128,  off);
        set(3, Wn2a,  pW2aT, FEATW,128,  FEATW,off);
        set(4, Wn2b,  pW2bT, 128,  2048, 128,  off);
        set(5, Wp1,   pWp1T, 2048, 128,  2048, off);
        set(6, Wp2,   pWp2T, 128,  2048, 128,  off);
        set(7, W_cg1, pWc1T, 49,   1225, KCG,  off);
        set(8, W_cg21,pWc2T, 49,   1225, KCG,  off);
        set(9, W_cg22,pWc3T, 49,   1225, KCG,  off);
        k_tmulti<<<off, 256>>>(P, 10);
    }

    // 1. xe = silu(x_edge @ Wd + bd)
    tgemm<1><<<dim3(1, 32, 1), 256, DYN_SMEM>>>(
        x_edge, nullptr, nullptr, pWdT, nullptr, nullptr, bd, nullptr, nullptr,
        p_xe, NEDGE, 128, 128, 128, 4, 4, 0, BIG);

    // 2. channel means (K padded to 64)
    k_xmym<<<NEDGE, 128>>>(x, eidx, p_xm, p_ym);

    // 3. CG bilinears: batched z=3  [4096,64] x [1225,64]^T -> t3 slabs
    tgemm<0><<<dim3(10, 32, 3), 256, DYN_SMEM>>>(
        p_xm, p_xm, p_ym, pWc1T, pWc2T, pWc3T, nullptr, nullptr, nullptr,
        p_t3, NEDGE, 1225, KCG, TPAD, 2, 2, 1, BIG);
    k_mid<<<NEDGE, 64>>>(p_ym, p_t3, p_mid);
    k_contract2<<<NEDGE, 64>>>(p_mid, p_t3 + (size_t)NEDGE * TPAD,
                               p_t3 + 2 * (size_t)NEDGE * TPAD, p_A);

    // 4+5. node_interactions batched: feat_all [8192, 2064]
    k_feat<<<2 * NEDGE, 128>>>(x, glovec, wign, eidx, p_feat);
    // a-stage: M=8192, K=2064, split-K z=4, dual-B at tile 32
    tgemm<0><<<dim3(1, 64, 4), 256, DYN_SMEM>>>(
        p_feat, nullptr, nullptr, pW1aT, pW2aT, nullptr, nullptr, nullptr, nullptr,
        p_part, 2 * NEDGE, 128, FEATW, 128, 65, 17, 0, 32);
    k_combine<1><<<(2 * NEDGE * 128 + 255) / 256, 256>>>(
        p_part, bn1a, bn2a, nullptr, p_h, 2 * NEDGE, 4, NEDGE);
    // b-stage: M=8192, N=2048, K=128, dual-B at tile 32
    tgemm<1><<<dim3(16, 64, 1), 256, DYN_SMEM>>>(
        p_h, nullptr, nullptr, pW1bT, pW2bT, nullptr, bn1b, bn2b, nullptr,
        p_h2, 2 * NEDGE, 2048, 128, 2048, 4, 4, 0, 32);
    k_sh2<<<NEDGE, 128>>>(wign, p_h2, p_sh);

    // 6. fused z-build + rotate
    k_rotmsg<<<NEDGE, 256>>>(x, eidx, p_A, p_sh, wigner, p_msg);

    // 7. edge MLP: msg @ Wp1 (K=2048, split-2) + xe epilogue, then @ Wp2
    tgemm<0><<<dim3(1, 96, 2), 256, DYN_SMEM>>>(
        p_msg, nullptr, nullptr, pWp1T, nullptr, nullptr, nullptr, nullptr, nullptr,
        p_part, NEDGE * NYR, 128, 2048, 128, 64, 32, 0, BIG);
    k_combine<2><<<(NEDGE * NYR * 128 + 255) / 256, 256>>>(
        p_part, bp1, bp1, p_xe, p_m1, NEDGE * NYR, 2, BIG);
    tgemm<1><<<dim3(16, 96, 1), 256, DYN_SMEM>>>(
        p_m1, nullptr, nullptr, pWp2T, nullptr, nullptr, bp2, nullptr, nullptr,
        p_m2, NEDGE * NYR, 2048, 128, 2048, 4, 4, 0, BIG);

    // 8. NY-mean + inverse rotation
    k_out<<<NEDGE, 256>>>(p_m2, winv, out);
}